// round 6
// baseline (speedup 1.0000x reference)
#include <cuda_runtime.h>
#include <cstdint>

typedef unsigned long long ull;

// ---------------- scratch (device globals; no allocation allowed) ----------
__device__ float g_W[64 * 1024];     // folded weights, layout [c][e] (e fastest)
__device__ float g_bias[16 * 64];    // [b][e]
__device__ float g_imp[64];
__device__ unsigned int g_cnt[64];

// ---------------- packed fp32x2 helpers ------------------------------------
#define PACK2(dst, f) asm("mov.b64 %0, {%1, %1};" : "=l"(dst) : "f"(f))
#define UNPACK2(lo, hi, src) asm("mov.b64 {%0, %1}, %2;" : "=f"(lo), "=f"(hi) : "l"(src))
#define FMA2(d, a, b, c) asm("fma.rn.f32x2 %0, %1, %2, %3;" : "=l"(d) : "l"(a), "l"(b), "l"(c))

__device__ __forceinline__ float warpReduceSum(float v) {
    #pragma unroll
    for (int o = 16; o; o >>= 1) v += __shfl_xor_sync(0xffffffffu, v, o);
    return v;
}

// ---------------- kernel 1: fused prologue ---------------------------------
// blocks [0, C/8): fold W columns [bx*8, bx*8+8) over full K (no atomics).
//   Writes g_W[c*64 + e] = sum_k Wg[e][k] * Wc[k][c].
// blocks [C/8, C/8+B): per-batch u = Wc[:,C:] @ cond_b, then bias = Wg @ u.
__global__ __launch_bounds__(256)
void k_prep(const float* __restrict__ Wg, const float* __restrict__ Wc,
            const float* __restrict__ cond, int C, int foldBlocks) {
    const int t = threadIdx.x;
    if ((int)blockIdx.x < foldBlocks) {
        const int c0 = blockIdx.x * 8;
        __shared__ float wg_s[64 * 65];   // [e][k]
        __shared__ float wc_s[64 * 9];    // [k][c-local]
        const int e = t & 63;
        const int ch = t >> 6;            // 0..3 -> cols ch*2, ch*2+1
        float a0 = 0.f, a1 = 0.f;
        for (int kc = 0; kc < C; kc += 64) {
            #pragma unroll
            for (int r = 0; r < 16; ++r) {
                int flat = r * 256 + t;
                int ee = flat >> 6, j = flat & 63;
                wg_s[ee * 65 + j] = Wg[(size_t)ee * C + kc + j];
            }
            #pragma unroll
            for (int r = 0; r < 2; ++r) {
                int flat = r * 256 + t;
                int j = flat >> 3, i = flat & 7;
                wc_s[j * 9 + i] = Wc[(size_t)(kc + j) * (2 * C) + c0 + i];
            }
            __syncthreads();
            #pragma unroll 8
            for (int j = 0; j < 64; ++j) {
                float w = wg_s[e * 65 + j];
                a0 += w * wc_s[j * 9 + ch * 2];
                a1 += w * wc_s[j * 9 + ch * 2 + 1];
            }
            __syncthreads();
        }
        g_W[(c0 + ch * 2) * 64 + e]     = a0;
        g_W[(c0 + ch * 2 + 1) * 64 + e] = a1;
    } else {
        const int b = blockIdx.x - foldBlocks;
        __shared__ float cs[1024];
        __shared__ float u_s[1024];
        const int w = t >> 5, lane = t & 31;
        for (int i = t; i < C; i += 256) cs[i] = cond[(size_t)b * C + i];
        if (b == 0 && t < 64) { g_imp[t] = 0.f; g_cnt[t] = 0u; }
        __syncthreads();
        for (int cp = w; cp < C; cp += 8) {
            const float* row = Wc + (size_t)cp * (2 * C) + C;
            float s = 0.f;
            for (int d = lane; d < C; d += 32) s += row[d] * cs[d];
            s = warpReduceSum(s);
            if (lane == 0) u_s[cp] = s;
        }
        __syncthreads();
        for (int e = w; e < 64; e += 8) {
            const float* wr = Wg + (size_t)e * C;
            float s = 0.f;
            for (int c = lane; c < C; c += 32) s += wr[c] * u_s[c];
            s = warpReduceSum(s);
            if (lane == 0) g_bias[b * 64 + e] = s;
        }
    }
}

// ---------------- kernel 2: main GEMM + fused router epilogue --------------
// (identical to the proven R1 k_main: 110us, fits registers, no spills)
#define BM 256
#define KC 16
#define XSS 17

__global__ __launch_bounds__(256)
void k_main(const float* __restrict__ x, float* __restrict__ out,
            int BT, int T, int C, int nkt) {
    __shared__ float xs[BM * XSS];
    __shared__ __align__(16) float ws[KC * 64];
    __shared__ float s_imp[64];
    __shared__ unsigned s_cnt[64];

    const int t = threadIdx.x;
    if (t < 64) { s_imp[t] = 0.f; s_cnt[t] = 0u; }

    const int tok0 = blockIdx.x * BM;
    const int c4 = t & 3, trow = t >> 2;
    const int eg = t & 7, tg = t >> 3;

    float4 xf[4];
    float4 wf;

    // prefetch tile 0
    {
        #pragma unroll
        for (int r = 0; r < 4; ++r) {
            int tok = tok0 + trow + r * 64;
            if (tok >= BT) tok = BT - 1;
            xf[r] = *(const float4*)(x + (size_t)tok * C + c4 * 4);
        }
        wf = ((const float4*)g_W)[t];
    }

    ull acc[8][4];
    #pragma unroll
    for (int i = 0; i < 8; ++i)
        #pragma unroll
        for (int p = 0; p < 4; ++p) acc[i][p] = 0ull;

    for (int kt = 0; kt < nkt; ++kt) {
        __syncthreads();
        #pragma unroll
        for (int r = 0; r < 4; ++r) {
            float* d = xs + (trow + r * 64) * XSS + c4 * 4;
            d[0] = xf[r].x; d[1] = xf[r].y; d[2] = xf[r].z; d[3] = xf[r].w;
        }
        ((float4*)ws)[t] = wf;
        __syncthreads();
        if (kt + 1 < nkt) {
            int kc = (kt + 1) * KC;
            #pragma unroll
            for (int r = 0; r < 4; ++r) {
                int tok = tok0 + trow + r * 64;
                if (tok >= BT) tok = BT - 1;
                xf[r] = *(const float4*)(x + (size_t)tok * C + kc + c4 * 4);
            }
            wf = ((const float4*)g_W)[(kt + 1) * 256 + t];
        }
        const float* xsp = xs + tg * 8 * XSS;
        #pragma unroll
        for (int k = 0; k < KC; ++k) {
            const ull* wrow = (const ull*)(ws + k * 64 + eg * 8);
            ull w0 = wrow[0], w1 = wrow[1], w2 = wrow[2], w3 = wrow[3];
            #pragma unroll
            for (int tt = 0; tt < 8; ++tt) {
                ull xp;
                PACK2(xp, xsp[tt * XSS + k]);
                FMA2(acc[tt][0], w0, xp, acc[tt][0]);
                FMA2(acc[tt][1], w1, xp, acc[tt][1]);
                FMA2(acc[tt][2], w2, xp, acc[tt][2]);
                FMA2(acc[tt][3], w3, xp, acc[tt][3]);
            }
        }
    }

    // -------------------- epilogue --------------------
    const int e0 = eg * 8;
    float* out_idx = out;
    float* out_sc  = out + (size_t)BT * 2;
    float* out_pr  = out + (size_t)BT * 4;
    float imp[8] = {0.f, 0.f, 0.f, 0.f, 0.f, 0.f, 0.f, 0.f};

    #pragma unroll
    for (int tt = 0; tt < 8; ++tt) {
        int tok = tok0 + tg * 8 + tt;
        bool valid = tok < BT;
        int tokc = valid ? tok : (BT - 1);
        int b = tokc / T;

        float lv[8];
        #pragma unroll
        for (int p = 0; p < 4; ++p) UNPACK2(lv[2 * p], lv[2 * p + 1], acc[tt][p]);
        #pragma unroll
        for (int j = 0; j < 8; ++j) lv[j] += g_bias[b * 64 + e0 + j];

        // local top-2 (ties keep lower index)
        float v1 = -1e30f, v2 = -1e30f;
        int i1 = 0, i2 = 0;
        #pragma unroll
        for (int j = 0; j < 8; ++j) {
            float v = lv[j];
            int e = e0 + j;
            if (v > v1) { v2 = v1; i2 = i1; v1 = v; i1 = e; }
            else if (v > v2) { v2 = v; i2 = e; }
        }
        // merge across the 8 lanes holding this token's 64 experts
        #pragma unroll
        for (int off = 1; off < 8; off <<= 1) {
            float ov1 = __shfl_xor_sync(0xffffffffu, v1, off);
            int   oi1 = __shfl_xor_sync(0xffffffffu, i1, off);
            float ov2 = __shfl_xor_sync(0xffffffffu, v2, off);
            int   oi2 = __shfl_xor_sync(0xffffffffu, i2, off);
            bool ob1 = (ov1 > v1) || (ov1 == v1 && oi1 < i1);
            if (ob1) {
                bool mb = (v1 > ov2) || (v1 == ov2 && i1 < oi2);
                if (mb) { v2 = v1; i2 = i1; } else { v2 = ov2; i2 = oi2; }
                v1 = ov1; i1 = oi1;
            } else {
                bool ob2 = (ov1 > v2) || (ov1 == v2 && oi1 < i2);
                if (ob2) { v2 = ov1; i2 = oi1; }
            }
        }

        // softmax over 64 (max == v1)
        float p[8], s = 0.f;
        #pragma unroll
        for (int j = 0; j < 8; ++j) { p[j] = __expf(lv[j] - v1); s += p[j]; }
        #pragma unroll
        for (int off = 1; off < 8; off <<= 1) s += __shfl_xor_sync(0xffffffffu, s, off);
        float inv = 1.0f / s;
        #pragma unroll
        for (int j = 0; j < 8; ++j) { p[j] *= inv; }

        if (valid) {
            #pragma unroll
            for (int j = 0; j < 8; ++j) imp[j] += p[j];
            float4* pp = (float4*)(out_pr + (size_t)tok * 64 + e0);
            pp[0] = make_float4(p[0], p[1], p[2], p[3]);
            pp[1] = make_float4(p[4], p[5], p[6], p[7]);
            if (eg == 0) {
                out_idx[tok * 2]     = (float)i1;
                out_idx[tok * 2 + 1] = (float)i2;
                float s1 = 1.0f / (1.0f + __expf(v2 - v1));
                out_sc[tok * 2]     = s1;
                out_sc[tok * 2 + 1] = 1.0f - s1;
                atomicAdd(&s_cnt[i1], 1u);
                atomicAdd(&s_cnt[i2], 1u);
            }
        }
    }

    #pragma unroll
    for (int j = 0; j < 8; ++j) atomicAdd(&s_imp[e0 + j], imp[j]);
    __syncthreads();
    if (t < 64) {
        atomicAdd(&g_imp[t], s_imp[t]);
        atomicAdd(&g_cnt[t], s_cnt[t]);
    }
}

// ---------------- kernel 3: finalize importance / load ---------------------
__global__ void k_final(float* __restrict__ out, int BT) {
    __shared__ float ssum;
    int e = threadIdx.x;
    if (e == 0) {
        float s = 0.f;
        for (int i = 0; i < 64; ++i) s += (float)g_cnt[i];
        ssum = s > 1.0f ? s : 1.0f;
    }
    __syncthreads();
    float* out_imp  = out + (size_t)BT * 4 + (size_t)BT * 64;
    float* out_load = out_imp + 64;
    if (e < 64) {
        out_imp[e]  = g_imp[e] / (float)BT;
        out_load[e] = (float)g_cnt[e] / ssum;
    }
}

// ---------------- launch ----------------------------------------------------
extern "C" void kernel_launch(void* const* d_in, const int* in_sizes, int n_in,
                              void* d_out, int out_size) {
    const float* x    = (const float*)d_in[0];
    const float* cond = (const float*)d_in[1];
    const float* Wg   = (const float*)d_in[2];
    const float* Wc   = (const float*)d_in[3];

    long long wcN = in_sizes[3];
    int C = 1;
    while ((long long)2 * C * C < wcN) C <<= 1;   // 1024
    int B = in_sizes[1] / C;                       // 4
    int T = in_sizes[0] / in_sizes[1];             // 8192
    int BT = B * T;

    int foldBlocks = C / 8;                        // 128
    k_prep<<<foldBlocks + B, 256>>>(Wg, Wc, cond, C, foldBlocks);
    k_main<<<(BT + BM - 1) / BM, 256>>>(x, (float*)d_out, BT, T, C, C / KC);
    k_final<<<1, 64>>>((float*)d_out, BT);
}

// round 7
// speedup vs baseline: 2.5121x; 2.5121x over previous
#include <cuda_runtime.h>
#include <cstdint>

typedef unsigned long long ull;

// ---------------- scratch (device globals; no allocation allowed) ----------
__device__ float g_W[64 * 1024];     // folded weights, layout [c][e] (e fastest)
__device__ float g_u[16 * 1024];     // [b][c] = Wc[:,C:] @ cond_b
__device__ float g_bias[16 * 64];    // [b][e]
__device__ float g_imp[64];
__device__ unsigned int g_cnt[64];

// ---------------- packed fp32x2 helpers ------------------------------------
#define PACK2(dst, f) asm("mov.b64 %0, {%1, %1};" : "=l"(dst) : "f"(f))
#define UNPACK2(lo, hi, src) asm("mov.b64 {%0, %1}, %2;" : "=f"(lo), "=f"(hi) : "l"(src))
#define FMA2(d, a, b, c) asm("fma.rn.f32x2 %0, %1, %2, %3;" : "=l"(d) : "l"(a), "l"(b), "l"(c))

__device__ __forceinline__ float warpReduceSum(float v) {
    #pragma unroll
    for (int o = 16; o; o >>= 1) v += __shfl_xor_sync(0xffffffffu, v, o);
    return v;
}

// ---------------- kernel 1: fused prologue ---------------------------------
// blocks [0, C/8): fold W columns [bx*8, bx*8+8) over full K (no atomics).
// blocks [C/8, C/8 + 32*B): u[b][rows] — 32 blocks per batch, 32 rows each,
//   4 interleaved dot-chains per warp (MLP=4).
__global__ __launch_bounds__(256)
void k_prep(const float* __restrict__ Wg, const float* __restrict__ Wc,
            const float* __restrict__ cond, int C, int foldBlocks) {
    const int t = threadIdx.x;
    if ((int)blockIdx.x < foldBlocks) {
        const int c0 = blockIdx.x * 8;
        __shared__ float wg_s[64 * 65];   // [e][k]
        __shared__ float wc_s[64 * 9];    // [k][c-local]
        const int e = t & 63;
        const int ch = t >> 6;            // 0..3 -> cols ch*2, ch*2+1
        float a0 = 0.f, a1 = 0.f;
        for (int kc = 0; kc < C; kc += 64) {
            #pragma unroll
            for (int r = 0; r < 16; ++r) {
                int flat = r * 256 + t;
                int ee = flat >> 6, j = flat & 63;
                wg_s[ee * 65 + j] = Wg[(size_t)ee * C + kc + j];
            }
            #pragma unroll
            for (int r = 0; r < 2; ++r) {
                int flat = r * 256 + t;
                int j = flat >> 3, i = flat & 7;
                wc_s[j * 9 + i] = Wc[(size_t)(kc + j) * (2 * C) + c0 + i];
            }
            __syncthreads();
            #pragma unroll 8
            for (int j = 0; j < 64; ++j) {
                float w = wg_s[e * 65 + j];
                a0 += w * wc_s[j * 9 + ch * 2];
                a1 += w * wc_s[j * 9 + ch * 2 + 1];
            }
            __syncthreads();
        }
        g_W[(c0 + ch * 2) * 64 + e]     = a0;
        g_W[(c0 + ch * 2 + 1) * 64 + e] = a1;
        if (blockIdx.x == 0 && t < 64) { g_imp[t] = 0.f; g_cnt[t] = 0u; }
    } else {
        // u blocks: 32 per batch, each covers 32 rows of u[b][:]
        const int ub = blockIdx.x - foldBlocks;
        const int b = ub >> 5;            // 32 blocks per batch
        const int slice = ub & 31;        // rows [slice*32, slice*32+32)
        __shared__ float cs[1024];
        const int w = t >> 5, lane = t & 31;
        for (int i = t; i < C; i += 256) cs[i] = cond[(size_t)b * C + i];
        __syncthreads();
        // warp w handles rows slice*32 + w + 8*rr, rr = 0..3 (4 chains, MLP=4)
        const int r0 = slice * 32 + w;
        const float* row0 = Wc + (size_t)(r0)      * (2 * C) + C;
        const float* row1 = Wc + (size_t)(r0 + 8)  * (2 * C) + C;
        const float* row2 = Wc + (size_t)(r0 + 16) * (2 * C) + C;
        const float* row3 = Wc + (size_t)(r0 + 24) * (2 * C) + C;
        float s0 = 0.f, s1 = 0.f, s2 = 0.f, s3 = 0.f;
        for (int d = lane; d < C; d += 32) {
            float cv = cs[d];
            s0 += row0[d] * cv;
            s1 += row1[d] * cv;
            s2 += row2[d] * cv;
            s3 += row3[d] * cv;
        }
        s0 = warpReduceSum(s0);
        s1 = warpReduceSum(s1);
        s2 = warpReduceSum(s2);
        s3 = warpReduceSum(s3);
        if (lane == 0) {
            g_u[b * C + r0]      = s0;
            g_u[b * C + r0 + 8]  = s1;
            g_u[b * C + r0 + 16] = s2;
            g_u[b * C + r0 + 24] = s3;
        }
    }
}

// ---------------- kernel 1b: bias[b][e] = Wg[e,:] @ u[b,:] -----------------
__global__ __launch_bounds__(256)
void k_bias(const float* __restrict__ Wg, int C) {
    const int e = blockIdx.x, b = blockIdx.y;
    const int t = threadIdx.x;
    __shared__ float red[8];
    const float* wr = Wg + (size_t)e * C;
    const float* ub = g_u + (size_t)b * C;
    float s = 0.f;
    for (int c = t; c < C; c += 256) s += wr[c] * ub[c];
    s = warpReduceSum(s);
    if ((t & 31) == 0) red[t >> 5] = s;
    __syncthreads();
    if (t == 0) {
        float v = 0.f;
        #pragma unroll
        for (int i = 0; i < 8; ++i) v += red[i];
        g_bias[b * 64 + e] = v;
    }
}

// ---------------- kernel 2: main GEMM + fused router epilogue --------------
// (byte-identical to the proven R1 k_main)
#define BM 256
#define KC 16
#define XSS 17

__global__ __launch_bounds__(256)
void k_main(const float* __restrict__ x, float* __restrict__ out,
            int BT, int T, int C, int nkt) {
    __shared__ float xs[BM * XSS];
    __shared__ __align__(16) float ws[KC * 64];
    __shared__ float s_imp[64];
    __shared__ unsigned s_cnt[64];

    const int t = threadIdx.x;
    if (t < 64) { s_imp[t] = 0.f; s_cnt[t] = 0u; }

    const int tok0 = blockIdx.x * BM;
    const int c4 = t & 3, trow = t >> 2;
    const int eg = t & 7, tg = t >> 3;

    float4 xf[4];
    float4 wf;

    {
        #pragma unroll
        for (int r = 0; r < 4; ++r) {
            int tok = tok0 + trow + r * 64;
            if (tok >= BT) tok = BT - 1;
            xf[r] = *(const float4*)(x + (size_t)tok * C + c4 * 4);
        }
        wf = ((const float4*)g_W)[t];
    }

    ull acc[8][4];
    #pragma unroll
    for (int i = 0; i < 8; ++i)
        #pragma unroll
        for (int p = 0; p < 4; ++p) acc[i][p] = 0ull;

    for (int kt = 0; kt < nkt; ++kt) {
        __syncthreads();
        #pragma unroll
        for (int r = 0; r < 4; ++r) {
            float* d = xs + (trow + r * 64) * XSS + c4 * 4;
            d[0] = xf[r].x; d[1] = xf[r].y; d[2] = xf[r].z; d[3] = xf[r].w;
        }
        ((float4*)ws)[t] = wf;
        __syncthreads();
        if (kt + 1 < nkt) {
            int kc = (kt + 1) * KC;
            #pragma unroll
            for (int r = 0; r < 4; ++r) {
                int tok = tok0 + trow + r * 64;
                if (tok >= BT) tok = BT - 1;
                xf[r] = *(const float4*)(x + (size_t)tok * C + kc + c4 * 4);
            }
            wf = ((const float4*)g_W)[(kt + 1) * 256 + t];
        }
        const float* xsp = xs + tg * 8 * XSS;
        #pragma unroll
        for (int k = 0; k < KC; ++k) {
            const ull* wrow = (const ull*)(ws + k * 64 + eg * 8);
            ull w0 = wrow[0], w1 = wrow[1], w2 = wrow[2], w3 = wrow[3];
            #pragma unroll
            for (int tt = 0; tt < 8; ++tt) {
                ull xp;
                PACK2(xp, xsp[tt * XSS + k]);
                FMA2(acc[tt][0], w0, xp, acc[tt][0]);
                FMA2(acc[tt][1], w1, xp, acc[tt][1]);
                FMA2(acc[tt][2], w2, xp, acc[tt][2]);
                FMA2(acc[tt][3], w3, xp, acc[tt][3]);
            }
        }
    }

    const int e0 = eg * 8;
    float* out_idx = out;
    float* out_sc  = out + (size_t)BT * 2;
    float* out_pr  = out + (size_t)BT * 4;
    float imp[8] = {0.f, 0.f, 0.f, 0.f, 0.f, 0.f, 0.f, 0.f};

    #pragma unroll
    for (int tt = 0; tt < 8; ++tt) {
        int tok = tok0 + tg * 8 + tt;
        bool valid = tok < BT;
        int tokc = valid ? tok : (BT - 1);
        int b = tokc / T;

        float lv[8];
        #pragma unroll
        for (int p = 0; p < 4; ++p) UNPACK2(lv[2 * p], lv[2 * p + 1], acc[tt][p]);
        #pragma unroll
        for (int j = 0; j < 8; ++j) lv[j] += g_bias[b * 64 + e0 + j];

        float v1 = -1e30f, v2 = -1e30f;
        int i1 = 0, i2 = 0;
        #pragma unroll
        for (int j = 0; j < 8; ++j) {
            float v = lv[j];
            int e = e0 + j;
            if (v > v1) { v2 = v1; i2 = i1; v1 = v; i1 = e; }
            else if (v > v2) { v2 = v; i2 = e; }
        }
        #pragma unroll
        for (int off = 1; off < 8; off <<= 1) {
            float ov1 = __shfl_xor_sync(0xffffffffu, v1, off);
            int   oi1 = __shfl_xor_sync(0xffffffffu, i1, off);
            float ov2 = __shfl_xor_sync(0xffffffffu, v2, off);
            int   oi2 = __shfl_xor_sync(0xffffffffu, i2, off);
            bool ob1 = (ov1 > v1) || (ov1 == v1 && oi1 < i1);
            if (ob1) {
                bool mb = (v1 > ov2) || (v1 == ov2 && i1 < oi2);
                if (mb) { v2 = v1; i2 = i1; } else { v2 = ov2; i2 = oi2; }
                v1 = ov1; i1 = oi1;
            } else {
                bool ob2 = (ov1 > v2) || (ov1 == v2 && oi1 < i2);
                if (ob2) { v2 = ov1; i2 = oi1; }
            }
        }

        float p[8], s = 0.f;
        #pragma unroll
        for (int j = 0; j < 8; ++j) { p[j] = __expf(lv[j] - v1); s += p[j]; }
        #pragma unroll
        for (int off = 1; off < 8; off <<= 1) s += __shfl_xor_sync(0xffffffffu, s, off);
        float inv = 1.0f / s;
        #pragma unroll
        for (int j = 0; j < 8; ++j) { p[j] *= inv; }

        if (valid) {
            #pragma unroll
            for (int j = 0; j < 8; ++j) imp[j] += p[j];
            float4* pp = (float4*)(out_pr + (size_t)tok * 64 + e0);
            pp[0] = make_float4(p[0], p[1], p[2], p[3]);
            pp[1] = make_float4(p[4], p[5], p[6], p[7]);
            if (eg == 0) {
                out_idx[tok * 2]     = (float)i1;
                out_idx[tok * 2 + 1] = (float)i2;
                float s1 = 1.0f / (1.0f + __expf(v2 - v1));
                out_sc[tok * 2]     = s1;
                out_sc[tok * 2 + 1] = 1.0f - s1;
                atomicAdd(&s_cnt[i1], 1u);
                atomicAdd(&s_cnt[i2], 1u);
            }
        }
    }

    #pragma unroll
    for (int j = 0; j < 8; ++j) atomicAdd(&s_imp[e0 + j], imp[j]);
    __syncthreads();
    if (t < 64) {
        atomicAdd(&g_imp[t], s_imp[t]);
        atomicAdd(&g_cnt[t], s_cnt[t]);
    }
}

// ---------------- kernel 3: finalize importance / load ---------------------
__global__ void k_final(float* __restrict__ out, int BT) {
    __shared__ float ssum;
    int e = threadIdx.x;
    if (e == 0) {
        float s = 0.f;
        for (int i = 0; i < 64; ++i) s += (float)g_cnt[i];
        ssum = s > 1.0f ? s : 1.0f;
    }
    __syncthreads();
    float* out_imp  = out + (size_t)BT * 4 + (size_t)BT * 64;
    float* out_load = out_imp + 64;
    if (e < 64) {
        out_imp[e]  = g_imp[e] / (float)BT;
        out_load[e] = (float)g_cnt[e] / ssum;
    }
}

// ---------------- launch ----------------------------------------------------
extern "C" void kernel_launch(void* const* d_in, const int* in_sizes, int n_in,
                              void* d_out, int out_size) {
    const float* x    = (const float*)d_in[0];
    const float* cond = (const float*)d_in[1];
    const float* Wg   = (const float*)d_in[2];
    const float* Wc   = (const float*)d_in[3];

    long long wcN = in_sizes[3];
    int C = 1;
    while ((long long)2 * C * C < wcN) C <<= 1;   // 1024
    int B = in_sizes[1] / C;                       // 4
    int T = in_sizes[0] / in_sizes[1];             // 8192
    int BT = B * T;

    int foldBlocks = C / 8;                        // 128
    int uBlocks = 32 * B;                          // 128
    k_prep<<<foldBlocks + uBlocks, 256>>>(Wg, Wc, cond, C, foldBlocks);
    k_bias<<<dim3(64, B), 256>>>(Wg, C);
    k_main<<<(BT + BM - 1) / BM, 256>>>(x, (float*)d_out, BT, T, C, C / KC);
    k_final<<<1, 64>>>((float*)d_out, BT);
}